// round 17
// baseline (speedup 1.0000x reference)
#include <cuda_runtime.h>
#include <cstdint>
#include <math_constants.h>

// KANLayer via FULL piecewise-linear collapse + bucketed segment search.
// Per edge e, F_e(x) = lw*(sum_k W3_k*leaky(a2_k(x))+b3) is exactly PWL.
// Build: per edge, sorted breakpoints bp[0..S-1], per-segment (A,B), and a
// 129-entry uint16 bucket index over [-5.5,5.5] (start[j] = #bp < bound_j).
// Eval: bucket -> short binary search -> one FMA.  B=1024,I=64,O=64,H=32.

constexpr int Bsz = 1024, Isz = 64, Osz = 64, Hsz = 32;
constexpr int NEDGE = Osz * Isz;       // 4096
constexpr int BPS = 1092;              // bp floats per edge (S<=1088 + sentinel)
constexpr int ABS = 1090;              // (A,B) float2 per edge (S+1 segments)
constexpr int NB  = 128;               // buckets
constexpr int BKS = 136;               // uint16 slots per edge (129 used, 16B-mult)
constexpr float XMIN = -5.5f;
constexpr float DXI  = NB / 11.0f;     // 1/bucket_width

__device__ __align__(16) float  g_bp[(size_t)NEDGE * BPS];
__device__ __align__(16) float2 g_ab[(size_t)NEDGE * ABS];
__device__ __align__(16) unsigned short g_bk[(size_t)NEDGE * BKS];
__device__ int g_S[NEDGE];

__device__ __forceinline__ float leaky(float v) { return fmaxf(v, 0.01f * v); }

__device__ __forceinline__ float wsum(float v) {
    #pragma unroll
    for (int m = 16; m > 0; m >>= 1) v += __shfl_xor_sync(~0u, v, m);
    return v;
}
__device__ __forceinline__ float wmin(float v) {
    #pragma unroll
    for (int m = 16; m > 0; m >>= 1) v = fminf(v, __shfl_xor_sync(~0u, v, m));
    return v;
}

// ---------------- build: 8 warps per block, one edge per warp ----------------
__global__ __launch_bounds__(256) void build_pwl(
    const float* __restrict__ W1, const float* __restrict__ b1,
    const float* __restrict__ W2, const float* __restrict__ b2,
    const float* __restrict__ W3, const float* __restrict__ b3,
    const float* __restrict__ lw)
{
    __shared__ float w2s_all[8][32 * 33];
    const int warp = threadIdx.x >> 5, lane = threadIdx.x & 31;
    const int e = blockIdx.x * 8 + warp;
    float* w2s = w2s_all[warp];

    // lane = h: threshold + kink deltas; left-of-threshold coefficients
    const float w1 = W1[e * Hsz + lane], bb1 = b1[e * Hsz + lane];
    float t, dp, dq;
    if (w1 != 0.f) { t = -bb1 / w1; const float ds = (w1 > 0.f) ? 0.99f : -0.99f; dp = ds * w1; dq = ds * bb1; }
    else           { t = CUDART_INF_F; dp = 0.f; dq = 0.f; }
    const float sL = (w1 > 0.f) ? 0.01f : ((w1 < 0.f) ? 1.f : ((bb1 >= 0.f) ? 1.f : 0.01f));
    const float aL = sL * w1, cL = sL * bb1;

    // bitonic sort (t, dp, dq, h) ascending by (t, h)
    float tk = t, sp = dp, sq = dq; int hh = lane;
    #pragma unroll
    for (int k2 = 2; k2 <= 32; k2 <<= 1)
        #pragma unroll
        for (int j = k2 >> 1; j > 0; j >>= 1) {
            const float ot = __shfl_xor_sync(~0u, tk, j);
            const float op = __shfl_xor_sync(~0u, sp, j);
            const float oq = __shfl_xor_sync(~0u, sq, j);
            const int   oh = __shfl_xor_sync(~0u, hh, j);
            const bool up = ((lane & k2) == 0), tm = ((lane & j) == 0) ? up : !up;
            const bool less = (tk < ot) || (tk == ot && hh < oh);
            if (tm != less) { tk = ot; sp = op; sq = oq; hh = oh; }
        }

    // stage W2[e][k][h] (stride 33)
    const float* W2g = W2 + (size_t)e * (Hsz * Hsz);
    #pragma unroll 8
    for (int r = 0; r < 32; ++r) w2s[r * 33 + lane] = W2g[r * 32 + lane];
    __syncwarp();

    // lane = k: base-segment (x -> -inf) coefficients of a2_k = P*x + Q
    const float w3p = lw[e] * W3[e * Hsz + lane];
    float P = 0.f, Q = b2[e * Hsz + lane];
    #pragma unroll
    for (int h = 0; h < 32; ++h) {
        const float wv = w2s[lane * 33 + h];
        P = fmaf(__shfl_sync(~0u, aL, h), wv, P);
        Q = fmaf(__shfl_sync(~0u, cL, h), wv, Q);
    }
    const float lwb3 = lw[e] * b3[e];

    float*  obp = g_bp + (size_t)e * BPS;
    float2* oab = g_ab + (size_t)e * ABS;
    int nseg = 0;
    float lo = -CUDART_INF_F;

    for (int j = 0; j <= 32; ++j) {
        const float hi = (j < 32) ? __shfl_sync(~0u, tk, j) : CUDART_INF_F;

        const float x0 = -Q / P;
        const bool valid = (P != 0.f) && (x0 > lo) && (x0 < hi);
        float xc = valid ? x0 : CUDART_INF_F;
        int remaining = __popc(__ballot_sync(~0u, valid));

        const float firstxc = wmin(xc);
        const float subhi = fminf(firstxc, hi);
        float xm;
        {
            const bool li = isinf(lo), hl = isinf(subhi);
            xm = (li && hl) ? 0.f : (li ? subhi - 1.f : (hl ? lo + 1.f : 0.5f * (lo + subhi)));
        }
        float s2 = (fmaf(P, xm, Q) > 0.f) ? 1.f : 0.01f;
        float A = wsum(w3p * s2 * P);
        float B = wsum(w3p * s2 * Q);

        if (lane == 0) {
            if (nseg > 0) obp[nseg - 1] = lo;
            oab[nseg] = make_float2(A, B + lwb3);
        }
        ++nseg;

        while (remaining > 0) {
            const float m = wmin(xc);
            const unsigned bal = __ballot_sync(~0u, xc == m);
            const int ks = __ffs(bal) - 1;
            const float Pk = __shfl_sync(~0u, P, ks), Qk = __shfl_sync(~0u, Q, ks);
            const float wk = __shfl_sync(~0u, w3p, ks), s2o = __shfl_sync(~0u, s2, ks);
            const float s2n = (s2o == 1.f) ? 0.01f : 1.f;
            if (lane == ks) { s2 = s2n; xc = CUDART_INF_F; }
            A += wk * (s2n - s2o) * Pk;
            B += wk * (s2n - s2o) * Qk;
            if (lane == 0) { obp[nseg - 1] = m; oab[nseg] = make_float2(A, B + lwb3); }
            ++nseg;
            --remaining;
        }

        if (j < 32) {
            const float dpj = __shfl_sync(~0u, sp, j), dqj = __shfl_sync(~0u, sq, j);
            const int hj = __shfl_sync(~0u, hh, j);
            const float wc = w2s[lane * 33 + hj];
            P = fmaf(dpj, wc, P); Q = fmaf(dqj, wc, Q);
        }
        lo = hi;
    }
    const int S = nseg - 1;                     // breakpoint count (uniform across lanes)
    if (lane == 0) { obp[S] = CUDART_INF_F; g_S[e] = S; }
    __threadfence_block();
    __syncwarp();

    // ---- bucket index: start[j] = #bp < XMIN + j/DXI ----
    unsigned short* obk = g_bk + (size_t)e * BKS;
    #pragma unroll
    for (int r = 0; r < 4; ++r) {
        const int j = lane + r * 32;            // 0..127
        int c = 0;
        if (j > 0) {
            const float bound = XMIN + (float)j / DXI;
            int l = 0, h = S;
            while (l < h) { const int m2 = (l + h) >> 1; if (obp[m2] < bound) l = m2 + 1; else h = m2; }
            c = l;
        }
        obk[j] = (unsigned short)c;
    }
    if (lane == 0) obk[NB] = (unsigned short)S;
}

// ---------------- eval ----------------
__device__ __forceinline__ uint32_t smem_u32(const void* p) {
    uint32_t a;
    asm("{ .reg .u64 t; cvta.to.shared.u64 t, %1; cvt.u32.u64 %0, t; }" : "=r"(a) : "l"(p));
    return a;
}
__device__ __forceinline__ void cpasync16(uint32_t s, const void* g) {
    asm volatile("cp.async.cg.shared.global [%0], [%1], 16;" :: "r"(s), "l"(g));
}

__global__ __launch_bounds__(128) void kan_eval(
    const float* __restrict__ x, const float* __restrict__ bw,
    float* __restrict__ out)
{
    __shared__ __align__(16) float  sbp[2][BPS];
    __shared__ __align__(16) float2 sab[2][ABS];
    __shared__ __align__(16) unsigned short sbk[2][BKS];
    const int tid = threadIdx.x, bt = blockIdx.x, o = blockIdx.y;
    const int e0 = o * Isz;
    const uint32_t bpA[2] = { smem_u32(sbp[0]), smem_u32(sbp[1]) };
    const uint32_t abA[2] = { smem_u32(sab[0]), smem_u32(sab[1]) };
    const uint32_t bkA[2] = { smem_u32(sbk[0]), smem_u32(sbk[1]) };

    // stage i = 0 into buffer 0
    int Scur = __ldg(&g_S[e0]);
    {
        const int nb = (((Scur + 1) * 4) + 15) & ~15;
        const char* g = (const char*)(g_bp + (size_t)e0 * BPS);
        for (int ofs = tid * 16; ofs < nb; ofs += 2048) cpasync16(bpA[0] + ofs, g + ofs);
        const int na = (((Scur + 1) * 8) + 15) & ~15;
        const char* ga = (const char*)(g_ab + (size_t)e0 * ABS);
        for (int ofs = tid * 16; ofs < na; ofs += 2048) cpasync16(abA[0] + ofs, ga + ofs);
        const char* gk = (const char*)(g_bk + (size_t)e0 * BKS);
        if (tid < 17) cpasync16(bkA[0] + tid * 16, gk + tid * 16);
        asm volatile("cp.async.commit_group;");
        asm volatile("cp.async.wait_group 0;");
    }
    __syncthreads();

    const int brow = bt * 128 + tid;
    const float* xr = x + (size_t)brow * Isz;
    float oa = 0.f;

    for (int i = 0; i < Isz; ++i) {
        // prefetch table i+1 into the other buffer (overlaps eval)
        int Snext = 0;
        if (i + 1 < Isz) {
            const int en = e0 + i + 1;
            Snext = __ldg(&g_S[en]);
            const uint32_t db = bpA[(i + 1) & 1], da = abA[(i + 1) & 1], dk = bkA[(i + 1) & 1];
            const int nb = (((Snext + 1) * 4) + 15) & ~15;
            const char* g = (const char*)(g_bp + (size_t)en * BPS);
            for (int ofs = tid * 16; ofs < nb; ofs += 2048) cpasync16(db + ofs, g + ofs);
            const int na = (((Snext + 1) * 8) + 15) & ~15;
            const char* ga = (const char*)(g_ab + (size_t)en * ABS);
            for (int ofs = tid * 16; ofs < na; ofs += 2048) cpasync16(da + ofs, ga + ofs);
            const char* gk = (const char*)(g_bk + (size_t)en * BKS);
            if (tid < 17) cpasync16(dk + tid * 16, gk + tid * 16);
        }
        asm volatile("cp.async.commit_group;");

        // evaluate current edge: bucket -> short binary search -> 1 FMA
        const float xv = xr[i];
        const float*          bp = sbp[i & 1];
        const float2*         ab = sab[i & 1];
        const unsigned short* bk = sbk[i & 1];

        int idx = __float2int_rd((xv - XMIN) * DXI);
        idx = min(max(idx, 0), NB - 1);
        int lo = bk[idx], hi = bk[idx + 1];
        while (lo < hi) {
            const int mid = (lo + hi) >> 1;
            if (bp[mid] < xv) lo = mid + 1; else hi = mid;
        }
        const float2 abv = ab[lo];
        oa += fmaf(abv.x, xv, abv.y) + __ldg(&bw[e0 + i]) * leaky(xv);

        Scur = Snext;
        asm volatile("cp.async.wait_group 0;");
        __syncthreads();
    }

    out[(size_t)brow * Osz + o] = oa;
}

extern "C" void kernel_launch(void* const* d_in, const int* in_sizes, int n_in,
                              void* d_out, int out_size)
{
    const float* x  = (const float*)d_in[0];
    const float* W1 = (const float*)d_in[1];
    const float* b1 = (const float*)d_in[2];
    const float* W2 = (const float*)d_in[3];
    const float* b2 = (const float*)d_in[4];
    const float* W3 = (const float*)d_in[5];
    const float* b3 = (const float*)d_in[6];
    const float* lw = (const float*)d_in[7];
    const float* bw = (const float*)d_in[8];
    float* out = (float*)d_out;

    build_pwl<<<NEDGE / 8, 256>>>(W1, b1, W2, b2, W3, b3, lw);
    dim3 grid(Bsz / 128, Osz);                 // (8, 64)
    kan_eval<<<grid, 128>>>(x, bw, out);
}